// round 13
// baseline (speedup 1.0000x reference)
#include <cuda_runtime.h>
#include <cuda_fp16.h>
#include <cstddef>
#include <cstdint>

#define VOCAB 100000
#define NB    16384
#define LSEQ  200
#define EMB   128
#define NCLS  1000

#define NCHUNK     4
#define CHUNK_ROWS (NB / NCHUNK)          // 4096 rows per chunk
#define POOL_GRID  (CHUNK_ROWS / 8)      // 512 pool blocks per chunk
#define GEMM_MX    (CHUNK_ROWS / 128)    // 32 m-blocks per chunk

// Scratch (alloc-free rule: __device__ globals).
__device__ __align__(16) __half g_table_h[(size_t)VOCAB * EMB];   // 25.6 MB
__device__ __align__(16) __half g_w_h[(size_t)NCLS * EMB];        // 256 KB
__device__ __align__(16) __half g_pooled_h[(size_t)NB * EMB];     // 4 MB

// ---------------------------------------------------------------------------
// Stage 0: convert table AND fc_w fp32 -> fp16 — proven R4/R7 version.
// ---------------------------------------------------------------------------
#define N_TBL4 ((size_t)VOCAB * EMB / 4)
#define N_W4   ((size_t)NCLS * EMB / 4)
#define N_ALL4 (N_TBL4 + N_W4)

__global__ __launch_bounds__(256) void convert_kernel(const float* __restrict__ t,
                                                      const float* __restrict__ W) {
    const size_t base = (size_t)blockIdx.x * 1024 + threadIdx.x;
    float4 v[4];
    bool   ok[4];
    #pragma unroll
    for (int i = 0; i < 4; ++i) {
        const size_t idx = base + (size_t)i * 256;
        ok[i] = idx < N_ALL4;
        if (ok[i])
            v[i] = (idx < N_TBL4) ? reinterpret_cast<const float4*>(t)[idx]
                                  : reinterpret_cast<const float4*>(W)[idx - N_TBL4];
    }
    #pragma unroll
    for (int i = 0; i < 4; ++i) {
        if (!ok[i]) continue;
        const size_t idx = base + (size_t)i * 256;
        union { __half2 h[2]; uint2 u; } pk;
        pk.h[0] = __floats2half2_rn(v[i].x, v[i].y);
        pk.h[1] = __floats2half2_rn(v[i].z, v[i].w);
        if (idx < N_TBL4) reinterpret_cast<uint2*>(g_table_h)[idx] = pk.u;
        else              reinterpret_cast<uint2*>(g_w_h)[idx - N_TBL4] = pk.u;
    }
}

// ---------------------------------------------------------------------------
// Stage 1: masked embedding-bag sum pool — EXACT R3 arithmetic, chunked.
// ---------------------------------------------------------------------------
__device__ __forceinline__ void hacc(float4& a, uint2 u) {
    const float2 f0 = __half22float2(*reinterpret_cast<__half2*>(&u.x));
    const float2 f1 = __half22float2(*reinterpret_cast<__half2*>(&u.y));
    a.x += f0.x; a.y += f0.y; a.z += f1.x; a.w += f1.y;
}

__global__ __launch_bounds__(256) void pool_kernel(const int* __restrict__ seq,
                                                   int row0) {
    __shared__ int s_tok[8][LSEQ];
    const int wid  = threadIdx.x >> 5;
    const int lane = threadIdx.x & 31;
    const int b0   = row0 + blockIdx.x * 8;

    for (int i = threadIdx.x; i < 8 * LSEQ; i += 256)
        s_tok[i / LSEQ][i % LSEQ] = seq[(size_t)b0 * LSEQ + i];
    __syncthreads();

    float4 a0 = {0,0,0,0}, a1 = {0,0,0,0}, a2 = {0,0,0,0}, a3 = {0,0,0,0};

    #pragma unroll 2
    for (int l = 0; l < LSEQ; l += 4) {
        const int t0 = s_tok[wid][l + 0];
        const int t1 = s_tok[wid][l + 1];
        const int t2 = s_tok[wid][l + 2];
        const int t3 = s_tok[wid][l + 3];
        if (t0) hacc(a0, reinterpret_cast<const uint2*>(g_table_h + (size_t)t0 * EMB)[lane]);
        if (t1) hacc(a1, reinterpret_cast<const uint2*>(g_table_h + (size_t)t1 * EMB)[lane]);
        if (t2) hacc(a2, reinterpret_cast<const uint2*>(g_table_h + (size_t)t2 * EMB)[lane]);
        if (t3) hacc(a3, reinterpret_cast<const uint2*>(g_table_h + (size_t)t3 * EMB)[lane]);
    }

    union { __half2 h[2]; uint2 u; } pk;
    pk.h[0] = __floats2half2_rn((a0.x + a1.x) + (a2.x + a3.x),
                                (a0.y + a1.y) + (a2.y + a3.y));
    pk.h[1] = __floats2half2_rn((a0.z + a1.z) + (a2.z + a3.z),
                                (a0.w + a1.w) + (a2.w + a3.w));
    reinterpret_cast<uint2*>(g_pooled_h + (size_t)(b0 + wid) * EMB)[lane] = pk.u;
}

// ---------------------------------------------------------------------------
// Stage 2: HMMA GEMM — EXACT R7 version, chunked by m-block offset.
// ---------------------------------------------------------------------------
__device__ __forceinline__ void mma16816(float* d,
                                         uint32_t a0, uint32_t a1, uint32_t a2, uint32_t a3,
                                         uint32_t b0, uint32_t b1) {
    asm volatile(
        "mma.sync.aligned.m16n8k16.row.col.f32.f16.f16.f32 "
        "{%0,%1,%2,%3}, {%4,%5,%6,%7}, {%8,%9}, {%0,%1,%2,%3};\n"
        : "+f"(d[0]), "+f"(d[1]), "+f"(d[2]), "+f"(d[3])
        : "r"(a0), "r"(a1), "r"(a2), "r"(a3), "r"(b0), "r"(b1));
}

__device__ __forceinline__ int swz(int row, int chunk) {
    return row * 128 + ((chunk ^ (row & 7)) << 3);
}

__global__ __launch_bounds__(256) void gemm_kernel(const float* __restrict__ bias,
                                                   float* __restrict__ out,
                                                   int mblk0) {
    __shared__ __half sA[128 * 128];   // 32 KB
    __shared__ __half sB[64 * 128];    // 16 KB

    const int tid  = threadIdx.x;
    const int lane = tid & 31;
    const int wid  = tid >> 5;
    const int wm   = wid >> 1;
    const int wn   = wid & 1;
    const int m0   = (mblk0 + blockIdx.x) * 128;
    const int nb0  = blockIdx.y * 128;

    const int lq = lane >> 2;
    const int lr = lane & 3;
    const int r0 = tid >> 4;
    const int c  = tid & 15;

    #pragma unroll
    for (int it = 0; it < 8; ++it) {
        const int r = r0 + it * 16;
        const uint4 v = reinterpret_cast<const uint4*>(
            g_pooled_h + (size_t)(m0 + r) * EMB)[c];
        *reinterpret_cast<uint4*>(&sA[swz(r, c)]) = v;
    }

    #pragma unroll
    for (int p = 0; p < 2; ++p) {
        const int n0 = nb0 + p * 64;

        if (p) __syncthreads();
        #pragma unroll
        for (int it = 0; it < 4; ++it) {
            const int r = r0 + it * 16;
            uint4 v = make_uint4(0u, 0u, 0u, 0u);
            if (n0 + r < NCLS)
                v = reinterpret_cast<const uint4*>(g_w_h + (size_t)(n0 + r) * EMB)[c];
            *reinterpret_cast<uint4*>(&sB[swz(r, c)]) = v;
        }
        __syncthreads();

        float acc[2][4][4] = {};

        #pragma unroll
        for (int ks = 0; ks < 8; ++ks) {
            uint32_t a[2][4];
            #pragma unroll
            for (int mi = 0; mi < 2; ++mi) {
                const int r  = wm * 32 + mi * 16 + lq;
                const int o0 = ((2 * ks)     ^ (r & 7)) * 8 + lr * 2;
                const int o1 = ((2 * ks + 1) ^ (r & 7)) * 8 + lr * 2;
                a[mi][0] = *reinterpret_cast<const uint32_t*>(&sA[r * 128 + o0]);
                a[mi][1] = *reinterpret_cast<const uint32_t*>(&sA[(r + 8) * 128 + o0]);
                a[mi][2] = *reinterpret_cast<const uint32_t*>(&sA[r * 128 + o1]);
                a[mi][3] = *reinterpret_cast<const uint32_t*>(&sA[(r + 8) * 128 + o1]);
            }
            #pragma unroll
            for (int nt = 0; nt < 4; ++nt) {
                const int n  = wn * 32 + nt * 8 + lq;
                const int o0 = ((2 * ks)     ^ (n & 7)) * 8 + lr * 2;
                const int o1 = ((2 * ks + 1) ^ (n & 7)) * 8 + lr * 2;
                const uint32_t b0 = *reinterpret_cast<const uint32_t*>(&sB[n * 128 + o0]);
                const uint32_t b1 = *reinterpret_cast<const uint32_t*>(&sB[n * 128 + o1]);
                #pragma unroll
                for (int mi = 0; mi < 2; ++mi)
                    mma16816(acc[mi][nt], a[mi][0], a[mi][1], a[mi][2], a[mi][3], b0, b1);
            }
        }

        #pragma unroll
        for (int nt = 0; nt < 4; ++nt) {
            const int n = n0 + wn * 32 + nt * 8 + lr * 2;
            if (n < NCLS) {
                const float2 b2 = *reinterpret_cast<const float2*>(bias + n);
                #pragma unroll
                for (int mi = 0; mi < 2; ++mi) {
                    const int m = m0 + wm * 32 + mi * 16 + lq;
                    float2 s0, s1;
                    s0.x = acc[mi][nt][0] + b2.x;
                    s0.y = acc[mi][nt][1] + b2.y;
                    s1.x = acc[mi][nt][2] + b2.x;
                    s1.y = acc[mi][nt][3] + b2.y;
                    *reinterpret_cast<float2*>(out + (size_t)m * NCLS + n)       = s0;
                    *reinterpret_cast<float2*>(out + (size_t)(m + 8) * NCLS + n) = s1;
                }
            }
        }
    }
}

// ---------------------------------------------------------------------------
// Launcher: chunked pipeline. Pools run serially on the null stream (full
// chip, full L2 — the configuration three rounds of evidence say is
// fastest); each chunk's GEMM runs on a non-blocking side stream gated by
// an event, overlapping the NEXT pool chunk. Fork/join is the standard
// graph-capture pattern; no device allocation anywhere.
// ---------------------------------------------------------------------------
extern "C" void kernel_launch(void* const* d_in, const int* in_sizes, int n_in,
                              void* d_out, int out_size) {
    const int*   seq   = (const int*)d_in[0];
    const float* table = (const float*)d_in[1];
    const float* W     = (const float*)d_in[2];
    const float* bias  = (const float*)d_in[3];
    float*       out   = (float*)d_out;

    // Fresh per call (called twice: correctness + capture). Not destroyed —
    // destroying a stream participating in capture would break the capture.
    cudaStream_t s2;
    cudaStreamCreateWithFlags(&s2, cudaStreamNonBlocking);
    cudaEvent_t ep[NCHUNK], ejoin;
    for (int i = 0; i < NCHUNK; ++i)
        cudaEventCreateWithFlags(&ep[i], cudaEventDisableTiming);
    cudaEventCreateWithFlags(&ejoin, cudaEventDisableTiming);

    const int conv_blocks = (int)((N_ALL4 + 1023) / 1024);
    convert_kernel<<<conv_blocks, 256>>>(table, W);

    for (int ch = 0; ch < NCHUNK; ++ch) {
        pool_kernel<<<POOL_GRID, 256>>>(seq, ch * CHUNK_ROWS);
        cudaEventRecord(ep[ch], 0);
        cudaStreamWaitEvent(s2, ep[ch], 0);
        dim3 grid(GEMM_MX, (NCLS + 127) / 128);
        gemm_kernel<<<grid, 256, 0, s2>>>(bias, out, ch * GEMM_MX);
    }

    // Join the side stream back so the harness's null-stream sync sees all work.
    cudaEventRecord(ejoin, s2);
    cudaStreamWaitEvent(0, ejoin, 0);
}

// round 14
// speedup vs baseline: 1.8086x; 1.8086x over previous
#include <cuda_runtime.h>
#include <cuda_fp16.h>
#include <cstddef>
#include <cstdint>

#define VOCAB 100000
#define NB    16384
#define LSEQ  200
#define EMB   128
#define NCLS  1000

// Scratch (alloc-free rule: __device__ globals).
__device__ __align__(16) __half g_table_h[(size_t)VOCAB * EMB];   // 25.6 MB
__device__ __align__(16) __half g_w_h[(size_t)NCLS * EMB];        // 256 KB
__device__ __align__(16) __half g_pooled_h[(size_t)NB * EMB];     // 4 MB

// ---------------------------------------------------------------------------
// Stage 0: convert table AND fc_w fp32 -> fp16 — proven version (12.2 us,
// DRAM-read floor; MLP_p1 = 4, regs 28, occ ~78%).
// ---------------------------------------------------------------------------
#define N_TBL4 ((size_t)VOCAB * EMB / 4)   // 3,200,000 float4
#define N_W4   ((size_t)NCLS * EMB / 4)    //    32,000 float4
#define N_ALL4 (N_TBL4 + N_W4)

__global__ __launch_bounds__(256) void convert_kernel(const float* __restrict__ t,
                                                      const float* __restrict__ W) {
    const size_t base = (size_t)blockIdx.x * 1024 + threadIdx.x;
    float4 v[4];
    bool   ok[4];
    #pragma unroll
    for (int i = 0; i < 4; ++i) {
        const size_t idx = base + (size_t)i * 256;
        ok[i] = idx < N_ALL4;
        if (ok[i])
            v[i] = (idx < N_TBL4) ? reinterpret_cast<const float4*>(t)[idx]
                                  : reinterpret_cast<const float4*>(W)[idx - N_TBL4];
    }
    #pragma unroll
    for (int i = 0; i < 4; ++i) {
        if (!ok[i]) continue;
        const size_t idx = base + (size_t)i * 256;
        union { __half2 h[2]; uint2 u; } pk;
        pk.h[0] = __floats2half2_rn(v[i].x, v[i].y);
        pk.h[1] = __floats2half2_rn(v[i].z, v[i].w);
        if (idx < N_TBL4) reinterpret_cast<uint2*>(g_table_h)[idx] = pk.u;
        else              reinterpret_cast<uint2*>(g_w_h)[idx - N_TBL4] = pk.u;
    }
}

// ---------------------------------------------------------------------------
// Stage 1: masked embedding-bag sum pool — proven R3 version. One warp per
// batch row; lane owns 4 dims (uint2 = half4 loads); fp32 accumulate.
// At the chip's aggregate-L2 throughput bound (~68 us) — invariant to LDG
// width, cache policy, and slice hashing (verified R8/R10/R11); the whole
// chip must be dedicated to it (overlap falsified R5/R6/R13).
// ---------------------------------------------------------------------------
__device__ __forceinline__ void hacc(float4& a, uint2 u) {
    const float2 f0 = __half22float2(*reinterpret_cast<__half2*>(&u.x));
    const float2 f1 = __half22float2(*reinterpret_cast<__half2*>(&u.y));
    a.x += f0.x; a.y += f0.y; a.z += f1.x; a.w += f1.y;
}

__global__ __launch_bounds__(256) void pool_kernel(const int* __restrict__ seq) {
    __shared__ int s_tok[8][LSEQ];
    const int wid  = threadIdx.x >> 5;
    const int lane = threadIdx.x & 31;
    const int b0   = blockIdx.x * 8;

    for (int i = threadIdx.x; i < 8 * LSEQ; i += 256)
        s_tok[i / LSEQ][i % LSEQ] = seq[(size_t)b0 * LSEQ + i];
    __syncthreads();

    float4 a0 = {0,0,0,0}, a1 = {0,0,0,0}, a2 = {0,0,0,0}, a3 = {0,0,0,0};

    #pragma unroll 2
    for (int l = 0; l < LSEQ; l += 4) {
        const int t0 = s_tok[wid][l + 0];
        const int t1 = s_tok[wid][l + 1];
        const int t2 = s_tok[wid][l + 2];
        const int t3 = s_tok[wid][l + 3];
        if (t0) hacc(a0, reinterpret_cast<const uint2*>(g_table_h + (size_t)t0 * EMB)[lane]);
        if (t1) hacc(a1, reinterpret_cast<const uint2*>(g_table_h + (size_t)t1 * EMB)[lane]);
        if (t2) hacc(a2, reinterpret_cast<const uint2*>(g_table_h + (size_t)t2 * EMB)[lane]);
        if (t3) hacc(a3, reinterpret_cast<const uint2*>(g_table_h + (size_t)t3 * EMB)[lane]);
    }

    union { __half2 h[2]; uint2 u; } pk;
    pk.h[0] = __floats2half2_rn((a0.x + a1.x) + (a2.x + a3.x),
                                (a0.y + a1.y) + (a2.y + a3.y));
    pk.h[1] = __floats2half2_rn((a0.z + a1.z) + (a2.z + a3.z),
                                (a0.w + a1.w) + (a2.w + a3.w));
    reinterpret_cast<uint2*>(g_pooled_h + (size_t)(b0 + wid) * EMB)[lane] = pk.u;
}

// ---------------------------------------------------------------------------
// Stage 2: HMMA GEMM — proven R7 version (store-bound floor ~16-18 us).
// Block computes 128x128 output via two 64-wide n-passes sharing one A tile.
// 8 warps as 4(m) x 2(n); warp tile 32x32; K=128 resident; XOR-swizzled smem.
// ---------------------------------------------------------------------------
__device__ __forceinline__ void mma16816(float* d,
                                         uint32_t a0, uint32_t a1, uint32_t a2, uint32_t a3,
                                         uint32_t b0, uint32_t b1) {
    asm volatile(
        "mma.sync.aligned.m16n8k16.row.col.f32.f16.f16.f32 "
        "{%0,%1,%2,%3}, {%4,%5,%6,%7}, {%8,%9}, {%0,%1,%2,%3};\n"
        : "+f"(d[0]), "+f"(d[1]), "+f"(d[2]), "+f"(d[3])
        : "r"(a0), "r"(a1), "r"(a2), "r"(a3), "r"(b0), "r"(b1));
}

__device__ __forceinline__ int swz(int row, int chunk) {
    return row * 128 + ((chunk ^ (row & 7)) << 3);
}

__global__ __launch_bounds__(256) void gemm_kernel(const float* __restrict__ bias,
                                                   float* __restrict__ out) {
    __shared__ __half sA[128 * 128];   // 32 KB
    __shared__ __half sB[64 * 128];    // 16 KB (reloaded between passes)

    const int tid  = threadIdx.x;
    const int lane = tid & 31;
    const int wid  = tid >> 5;
    const int wm   = wid >> 1;         // 0..3 (m, 32 rows each)
    const int wn   = wid & 1;          // 0..1 (n, 32 cols each)
    const int m0   = blockIdx.x * 128;
    const int nb0  = blockIdx.y * 128;

    const int lq = lane >> 2;
    const int lr = lane & 3;
    const int r0 = tid >> 4;
    const int c  = tid & 15;

    #pragma unroll
    for (int it = 0; it < 8; ++it) {
        const int r = r0 + it * 16;
        const uint4 v = reinterpret_cast<const uint4*>(
            g_pooled_h + (size_t)(m0 + r) * EMB)[c];
        *reinterpret_cast<uint4*>(&sA[swz(r, c)]) = v;
    }

    #pragma unroll
    for (int p = 0; p < 2; ++p) {
        const int n0 = nb0 + p * 64;

        if (p) __syncthreads();
        #pragma unroll
        for (int it = 0; it < 4; ++it) {
            const int r = r0 + it * 16;
            uint4 v = make_uint4(0u, 0u, 0u, 0u);
            if (n0 + r < NCLS)
                v = reinterpret_cast<const uint4*>(g_w_h + (size_t)(n0 + r) * EMB)[c];
            *reinterpret_cast<uint4*>(&sB[swz(r, c)]) = v;
        }
        __syncthreads();

        float acc[2][4][4] = {};

        #pragma unroll
        for (int ks = 0; ks < 8; ++ks) {
            uint32_t a[2][4];
            #pragma unroll
            for (int mi = 0; mi < 2; ++mi) {
                const int r  = wm * 32 + mi * 16 + lq;
                const int o0 = ((2 * ks)     ^ (r & 7)) * 8 + lr * 2;
                const int o1 = ((2 * ks + 1) ^ (r & 7)) * 8 + lr * 2;
                a[mi][0] = *reinterpret_cast<const uint32_t*>(&sA[r * 128 + o0]);
                a[mi][1] = *reinterpret_cast<const uint32_t*>(&sA[(r + 8) * 128 + o0]);
                a[mi][2] = *reinterpret_cast<const uint32_t*>(&sA[r * 128 + o1]);
                a[mi][3] = *reinterpret_cast<const uint32_t*>(&sA[(r + 8) * 128 + o1]);
            }
            #pragma unroll
            for (int nt = 0; nt < 4; ++nt) {
                const int n  = wn * 32 + nt * 8 + lq;
                const int o0 = ((2 * ks)     ^ (n & 7)) * 8 + lr * 2;
                const int o1 = ((2 * ks + 1) ^ (n & 7)) * 8 + lr * 2;
                const uint32_t b0 = *reinterpret_cast<const uint32_t*>(&sB[n * 128 + o0]);
                const uint32_t b1 = *reinterpret_cast<const uint32_t*>(&sB[n * 128 + o1]);
                #pragma unroll
                for (int mi = 0; mi < 2; ++mi)
                    mma16816(acc[mi][nt], a[mi][0], a[mi][1], a[mi][2], a[mi][3], b0, b1);
            }
        }

        #pragma unroll
        for (int nt = 0; nt < 4; ++nt) {
            const int n = n0 + wn * 32 + nt * 8 + lr * 2;
            if (n < NCLS) {
                const float2 b2 = *reinterpret_cast<const float2*>(bias + n);
                #pragma unroll
                for (int mi = 0; mi < 2; ++mi) {
                    const int m = m0 + wm * 32 + mi * 16 + lq;
                    float2 s0, s1;
                    s0.x = acc[mi][nt][0] + b2.x;
                    s0.y = acc[mi][nt][1] + b2.y;
                    s1.x = acc[mi][nt][2] + b2.x;
                    s1.y = acc[mi][nt][3] + b2.y;
                    *reinterpret_cast<float2*>(out + (size_t)m * NCLS + n)       = s0;
                    *reinterpret_cast<float2*>(out + (size_t)(m + 8) * NCLS + n) = s1;
                }
            }
        }
    }
}

extern "C" void kernel_launch(void* const* d_in, const int* in_sizes, int n_in,
                              void* d_out, int out_size) {
    const int*   seq   = (const int*)d_in[0];
    const float* table = (const float*)d_in[1];
    const float* W     = (const float*)d_in[2];
    const float* bias  = (const float*)d_in[3];
    float*       out   = (float*)d_out;

    const int conv_blocks = (int)((N_ALL4 + 1023) / 1024);
    convert_kernel<<<conv_blocks, 256>>>(table, W);

    pool_kernel<<<NB / 8, 256>>>(seq);

    dim3 grid(NB / 128, (NCLS + 127) / 128);
    gemm_kernel<<<grid, 256>>>(bias, out);
}